// round 1
// baseline (speedup 1.0000x reference)
#include <cuda_runtime.h>
#include <cstdint>
#include <math.h>

#define NREL   3
#define NNODES 65536
#define FEAT   512
#define EMB    512
#define MTOT   (4*NNODES)   // 262144 rows: [0,N) = center, [N,4N) = neigh r*N+n

// ---- scratch (static device globals; no allocations allowed) ----
__device__ float  g_H[(size_t)MTOT * EMB];   // 512 MB: H = X @ W^T, row-major
__device__ float  g_u[2*EMB];                // u_c = W^T a_c, u_n = W^T a_n
__device__ float  g_e[MTOT];                 // e = X @ u
__device__ float  g_att[NREL*NNODES];        // attention [r][n]
__device__ double g_s[NREL];                 // per-relation attention sums

__device__ __forceinline__ unsigned f2tf32(float x) {
    unsigned r;
    asm("cvt.rna.tf32.f32 %0, %1;" : "=r"(r) : "f"(x));
    return r;
}

__device__ __forceinline__ void cvt4(float* dst, float4 v) {
    dst[0] = __uint_as_float(f2tf32(v.x));
    dst[1] = __uint_as_float(f2tf32(v.y));
    dst[2] = __uint_as_float(f2tf32(v.z));
    dst[3] = __uint_as_float(f2tf32(v.w));
}

__device__ __forceinline__ void mma_tf32(float c[4], const unsigned a[4], const unsigned b[2]) {
    asm volatile(
        "mma.sync.aligned.m16n8k8.row.col.f32.tf32.tf32.f32 "
        "{%0,%1,%2,%3}, {%4,%5,%6,%7}, {%8,%9}, {%0,%1,%2,%3};\n"
        : "+f"(c[0]), "+f"(c[1]), "+f"(c[2]), "+f"(c[3])
        : "r"(a[0]), "r"(a[1]), "r"(a[2]), "r"(a[3]), "r"(b[0]), "r"(b[1]));
}

// ---- kernel 0: u_c = W^T a_c, u_n = W^T a_n; zero relation sums ----
__global__ void prep_kernel(const float* __restrict__ W, const float* __restrict__ a) {
    int f = blockIdx.x * blockDim.x + threadIdx.x;   // 0..511
    float sc = 0.f, sn = 0.f;
    for (int e = 0; e < EMB; ++e) {
        float w = W[(size_t)e * FEAT + f];
        sc += w * a[e];
        sn += w * a[EMB + e];
    }
    g_u[f]       = sc;
    g_u[EMB + f] = sn;
    if (f < NREL) g_s[f] = 0.0;
}

// ---- kernel 1: TF32 GEMM  H[row][col] = sum_k X[row][k] * W[col][k]
//      BM=128, BN=128, BK=16; 8 warps (2m x 4n), warp tile 64x32.
//      blockIdx.x == 0 CTAs also accumulate e[row] = sum_k X[row][k]*u[k]. ----
__global__ __launch_bounds__(256)
void gemm_kernel(const float* __restrict__ selfF,
                 const float* __restrict__ neighF,
                 const float* __restrict__ W) {
    __shared__ float As[128 * 20];   // [row][k], stride 20 (conflict-free for frag loads)
    __shared__ float Bs[128 * 20];   // [col][k]
    __shared__ float Us[512];

    const int tid  = threadIdx.x;
    const int wid  = tid >> 5, lane = tid & 31;
    const int wm   = wid >> 2;   // 0..1 : row offset wm*64
    const int wn   = wid & 3;    // 0..3 : col offset wn*32
    const int g    = lane >> 2;  // groupID 0..7
    const int tg   = lane & 3;   // thread-in-group

    const size_t rowBlk = (size_t)blockIdx.y * 128;
    const int    colBlk = blockIdx.x * 128;
    const float* Aptr = (rowBlk < NNODES) ? (selfF + rowBlk * FEAT)
                                          : (neighF + (rowBlk - NNODES) * FEAT);
    const float* Bp = W + (size_t)colBlk * FEAT;

    if (blockIdx.x == 0) {
        const float* u = (rowBlk < NNODES) ? g_u : (g_u + EMB);
        for (int i = tid; i < 512; i += 256) Us[i] = u[i];
    }

    const int r0 = tid >> 2;           // 0..63
    const int kq = (tid & 3) * 4;      // k quad offset

    // prologue: tile 0 -> smem
    {
        float4 a0v = *(const float4*)(Aptr + (size_t)r0 * FEAT + kq);
        float4 a1v = *(const float4*)(Aptr + (size_t)(r0 + 64) * FEAT + kq);
        float4 b0v = *(const float4*)(Bp   + (size_t)r0 * FEAT + kq);
        float4 b1v = *(const float4*)(Bp   + (size_t)(r0 + 64) * FEAT + kq);
        cvt4(&As[r0 * 20 + kq], a0v);  cvt4(&As[(r0 + 64) * 20 + kq], a1v);
        cvt4(&Bs[r0 * 20 + kq], b0v);  cvt4(&Bs[(r0 + 64) * 20 + kq], b1v);
    }
    __syncthreads();

    float acc[4][4][4];
    #pragma unroll
    for (int i = 0; i < 4; ++i)
        #pragma unroll
        for (int j = 0; j < 4; ++j)
            #pragma unroll
            for (int q = 0; q < 4; ++q) acc[i][j][q] = 0.f;
    float eacc = 0.f;

    #pragma unroll 1
    for (int t = 0; t < 32; ++t) {
        float4 na0, na1, nb0, nb1;
        if (t < 31) {
            int k0 = (t + 1) * 16;
            na0 = *(const float4*)(Aptr + (size_t)r0 * FEAT + k0 + kq);
            na1 = *(const float4*)(Aptr + (size_t)(r0 + 64) * FEAT + k0 + kq);
            nb0 = *(const float4*)(Bp   + (size_t)r0 * FEAT + k0 + kq);
            nb1 = *(const float4*)(Bp   + (size_t)(r0 + 64) * FEAT + k0 + kq);
        }

        #pragma unroll
        for (int kk = 0; kk < 2; ++kk) {
            unsigned af[4][4], bf[4][2];
            #pragma unroll
            for (int mt = 0; mt < 4; ++mt) {
                int rr = wm * 64 + mt * 16;
                af[mt][0] = __float_as_uint(As[(rr + g    ) * 20 + kk * 8 + tg]);
                af[mt][1] = __float_as_uint(As[(rr + g + 8) * 20 + kk * 8 + tg]);
                af[mt][2] = __float_as_uint(As[(rr + g    ) * 20 + kk * 8 + tg + 4]);
                af[mt][3] = __float_as_uint(As[(rr + g + 8) * 20 + kk * 8 + tg + 4]);
            }
            #pragma unroll
            for (int nt = 0; nt < 4; ++nt) {
                int cc = wn * 32 + nt * 8;
                bf[nt][0] = __float_as_uint(Bs[(cc + g) * 20 + kk * 8 + tg]);
                bf[nt][1] = __float_as_uint(Bs[(cc + g) * 20 + kk * 8 + tg + 4]);
            }
            #pragma unroll
            for (int mt = 0; mt < 4; ++mt)
                #pragma unroll
                for (int nt = 0; nt < 4; ++nt)
                    mma_tf32(acc[mt][nt], af[mt], bf[nt]);
        }

        // fused e = X @ u accumulation (only one CTA column does this)
        if (blockIdx.x == 0) {
            int er = tid >> 1, kb = (tid & 1) * 8;
            #pragma unroll
            for (int i = 0; i < 8; ++i)
                eacc += As[er * 20 + kb + i] * Us[t * 16 + kb + i];
        }

        if (t < 31) {
            __syncthreads();
            cvt4(&As[r0 * 20 + kq], na0);  cvt4(&As[(r0 + 64) * 20 + kq], na1);
            cvt4(&Bs[r0 * 20 + kq], nb0);  cvt4(&Bs[(r0 + 64) * 20 + kq], nb1);
            __syncthreads();
        }
    }

    // epilogue: write H tile
    #pragma unroll
    for (int mt = 0; mt < 4; ++mt) {
        size_t row = rowBlk + (size_t)(wm * 64 + mt * 16 + g);
        #pragma unroll
        for (int nt = 0; nt < 4; ++nt) {
            int col = colBlk + wn * 32 + nt * 8 + 2 * tg;
            float2 v0 = make_float2(acc[mt][nt][0], acc[mt][nt][1]);
            float2 v1 = make_float2(acc[mt][nt][2], acc[mt][nt][3]);
            *(float2*)&g_H[row * EMB + col]       = v0;
            *(float2*)&g_H[(row + 8) * EMB + col] = v1;
        }
    }
    if (blockIdx.x == 0) {
        eacc += __shfl_xor_sync(0xffffffffu, eacc, 1);
        if ((tid & 1) == 0) g_e[rowBlk + (tid >> 1)] = eacc;
    }
}

// ---- kernel 2: per-node attention softmax over 3 relations + global sums ----
__global__ void attn_kernel() {
    int n = blockIdx.x * blockDim.x + threadIdx.x;
    float ec = g_e[n];
    float v0 = ec + g_e[NNODES + n];
    float v1 = ec + g_e[2 * NNODES + n];
    float v2 = ec + g_e[3 * NNODES + n];
    v0 = v0 > 0.f ? v0 : 0.2f * v0;
    v1 = v1 > 0.f ? v1 : 0.2f * v1;
    v2 = v2 > 0.f ? v2 : 0.2f * v2;
    float mx = fmaxf(v0, fmaxf(v1, v2));
    float e0 = expf(v0 - mx), e1 = expf(v1 - mx), e2 = expf(v2 - mx);
    float inv = 1.f / (e0 + e1 + e2);
    float a0 = e0 * inv, a1 = e1 * inv, a2 = e2 * inv;
    g_att[n]              = a0;
    g_att[NNODES + n]     = a1;
    g_att[2 * NNODES + n] = a2;

    #pragma unroll
    for (int o = 16; o; o >>= 1) {
        a0 += __shfl_xor_sync(0xffffffffu, a0, o);
        a1 += __shfl_xor_sync(0xffffffffu, a1, o);
        a2 += __shfl_xor_sync(0xffffffffu, a2, o);
    }
    __shared__ float s0[8], s1[8], s2[8];
    int w = threadIdx.x >> 5;
    if ((threadIdx.x & 31) == 0) { s0[w] = a0; s1[w] = a1; s2[w] = a2; }
    __syncthreads();
    if (threadIdx.x == 0) {
        float t0 = 0.f, t1 = 0.f, t2 = 0.f;
        #pragma unroll
        for (int i = 0; i < 8; ++i) { t0 += s0[i]; t1 += s1[i]; t2 += s2[i]; }
        atomicAdd(&g_s[0], (double)t0);
        atomicAdd(&g_s[1], (double)t1);
        atomicAdd(&g_s[2], (double)t2);
    }
}

// ---- kernel 3: combined[e][n] = relu(Hc[n][e] + sum_r att[r][n]*Hn[r][n][e])
//      32x32 shared-memory transpose tile, coalesced reads and writes ----
__global__ void combine_kernel(float* __restrict__ out) {
    __shared__ float sh[32][33];
    int nb = blockIdx.x * 32, eb = blockIdx.y * 32;
    int tx = threadIdx.x, ty = threadIdx.y;   // 32 x 8

    #pragma unroll
    for (int j = 0; j < 4; ++j) {
        int nl = ty + j * 8;
        size_t n = (size_t)(nb + nl);
        int e = eb + tx;
        float v = g_H[n * EMB + e];
        #pragma unroll
        for (int r = 0; r < NREL; ++r) {
            float aw = g_att[r * NNODES + (nb + nl)];
            v += aw * g_H[((size_t)NNODES * (1 + r) + n) * EMB + e];
        }
        sh[nl][tx] = v > 0.f ? v : 0.f;
    }
    __syncthreads();
    #pragma unroll
    for (int j = 0; j < 4; ++j) {
        int el = ty + j * 8;
        out[(size_t)(eb + el) * NNODES + nb + tx] = sh[tx][el];
    }
}

// ---- kernel 4: softmax over 3 relation sums -> tail of output ----
__global__ void attout_kernel(float* __restrict__ out) {
    double s0 = g_s[0], s1 = g_s[1], s2 = g_s[2];
    double m = fmax(s0, fmax(s1, s2));
    double e0 = exp(s0 - m), e1 = exp(s1 - m), e2 = exp(s2 - m);
    double inv = 1.0 / (e0 + e1 + e2);
    size_t base = (size_t)EMB * NNODES;
    out[base + 0] = (float)(e0 * inv);
    out[base + 1] = (float)(e1 * inv);
    out[base + 2] = (float)(e2 * inv);
}

extern "C" void kernel_launch(void* const* d_in, const int* in_sizes, int n_in,
                              void* d_out, int out_size) {
    const float* selfF  = (const float*)d_in[0];
    const float* neighF = (const float*)d_in[1];
    const float* W      = (const float*)d_in[2];
    const float* a      = (const float*)d_in[3];
    float* out = (float*)d_out;

    prep_kernel<<<4, 128>>>(W, a);

    dim3 ggrid(EMB / 128, MTOT / 128);   // (4, 2048)
    gemm_kernel<<<ggrid, 256>>>(selfF, neighF, W);

    attn_kernel<<<NNODES / 256, 256>>>();

    dim3 cgrid(NNODES / 32, EMB / 32);   // (2048, 16)
    combine_kernel<<<cgrid, dim3(32, 8)>>>(out);

    attout_kernel<<<1, 1>>>(out);
}

// round 3
// speedup vs baseline: 2.9433x; 2.9433x over previous
#include <cuda_runtime.h>
#include <cstdint>
#include <math.h>

#define NREL   3
#define NNODES 65536
#define FEAT   512
#define EMB    512

// ---- scratch (static device globals; no allocations allowed) ----
__device__ float  g_mix[(size_t)NNODES * FEAT];  // 134 MB: self + sum_r att*neigh
__device__ float  g_u[2*EMB];                    // u_c = W^T a_c, u_n = W^T a_n
__device__ double g_s[NREL];                     // per-relation attention sums

__device__ __forceinline__ unsigned f2tf32(float x) {
    unsigned r;
    asm("cvt.rna.tf32.f32 %0, %1;" : "=r"(r) : "f"(x));
    return r;
}

__device__ __forceinline__ void cvt4(float* dst, float4 v) {
    dst[0] = __uint_as_float(f2tf32(v.x));
    dst[1] = __uint_as_float(f2tf32(v.y));
    dst[2] = __uint_as_float(f2tf32(v.z));
    dst[3] = __uint_as_float(f2tf32(v.w));
}

__device__ __forceinline__ void mma_tf32(float c[4], const unsigned a[4], const unsigned b[2]) {
    asm volatile(
        "mma.sync.aligned.m16n8k8.row.col.f32.tf32.tf32.f32 "
        "{%0,%1,%2,%3}, {%4,%5,%6,%7}, {%8,%9}, {%0,%1,%2,%3};\n"
        : "+f"(c[0]), "+f"(c[1]), "+f"(c[2]), "+f"(c[3])
        : "r"(a[0]), "r"(a[1]), "r"(a[2]), "r"(a[3]), "r"(b[0]), "r"(b[1]));
}

// ---- kernel 0: u_c = W^T a_c, u_n = W^T a_n; zero relation sums ----
__global__ void prep_kernel(const float* __restrict__ W, const float* __restrict__ a) {
    int f = blockIdx.x * blockDim.x + threadIdx.x;   // 0..511
    float sc = 0.f, sn = 0.f;
    for (int e = 0; e < EMB; ++e) {
        float w = W[(size_t)e * FEAT + f];
        sc += w * a[e];
        sn += w * a[EMB + e];
    }
    g_u[f]       = sc;
    g_u[EMB + f] = sn;
    if (f < NREL) g_s[f] = 0.0;
}

// ---- kernel 1: per-node attention + feature mix (one warp per node) ----
__global__ __launch_bounds__(256)
void mix_kernel(const float* __restrict__ selfF, const float* __restrict__ neighF) {
    __shared__ float bs[NREL];
    const int tid  = threadIdx.x;
    const int lane = tid & 31;
    const int n    = blockIdx.x * 8 + (tid >> 5);

    if (tid < NREL) bs[tid] = 0.f;
    __syncthreads();

    const float4* sp  = (const float4*)(selfF + (size_t)n * FEAT);
    const float4* np0 = (const float4*)(neighF + ((size_t)0 * NNODES + n) * FEAT);
    const float4* np1 = (const float4*)(neighF + ((size_t)1 * NNODES + n) * FEAT);
    const float4* np2 = (const float4*)(neighF + ((size_t)2 * NNODES + n) * FEAT);
    const float4* ucp = (const float4*)(g_u);
    const float4* unp = (const float4*)(g_u + EMB);

    float4 s[4], n0[4], n1[4], n2[4], uc[4], un[4];
    #pragma unroll
    for (int j = 0; j < 4; ++j) {
        int idx = lane + 32 * j;
        s[j]  = sp[idx];
        n0[j] = np0[idx];
        n1[j] = np1[idx];
        n2[j] = np2[idx];
        uc[j] = ucp[idx];
        un[j] = unp[idx];
    }

    float ec = 0.f, e0 = 0.f, e1 = 0.f, e2 = 0.f;
    #pragma unroll
    for (int j = 0; j < 4; ++j) {
        ec += s[j].x*uc[j].x + s[j].y*uc[j].y + s[j].z*uc[j].z + s[j].w*uc[j].w;
        e0 += n0[j].x*un[j].x + n0[j].y*un[j].y + n0[j].z*un[j].z + n0[j].w*un[j].w;
        e1 += n1[j].x*un[j].x + n1[j].y*un[j].y + n1[j].z*un[j].z + n1[j].w*un[j].w;
        e2 += n2[j].x*un[j].x + n2[j].y*un[j].y + n2[j].z*un[j].z + n2[j].w*un[j].w;
    }
    #pragma unroll
    for (int o = 16; o; o >>= 1) {
        ec += __shfl_xor_sync(0xffffffffu, ec, o);
        e0 += __shfl_xor_sync(0xffffffffu, e0, o);
        e1 += __shfl_xor_sync(0xffffffffu, e1, o);
        e2 += __shfl_xor_sync(0xffffffffu, e2, o);
    }

    float v0 = ec + e0, v1 = ec + e1, v2 = ec + e2;
    v0 = v0 > 0.f ? v0 : 0.2f * v0;
    v1 = v1 > 0.f ? v1 : 0.2f * v1;
    v2 = v2 > 0.f ? v2 : 0.2f * v2;
    float mx = fmaxf(v0, fmaxf(v1, v2));
    float x0 = expf(v0 - mx), x1 = expf(v1 - mx), x2 = expf(v2 - mx);
    float inv = 1.f / (x0 + x1 + x2);
    float a0 = x0 * inv, a1 = x1 * inv, a2 = x2 * inv;

    float4* mp = (float4*)(g_mix + (size_t)n * FEAT);
    #pragma unroll
    for (int j = 0; j < 4; ++j) {
        float4 m;
        m.x = s[j].x + a0*n0[j].x + a1*n1[j].x + a2*n2[j].x;
        m.y = s[j].y + a0*n0[j].y + a1*n1[j].y + a2*n2[j].y;
        m.z = s[j].z + a0*n0[j].z + a1*n1[j].z + a2*n2[j].z;
        m.w = s[j].w + a0*n0[j].w + a1*n1[j].w + a2*n2[j].w;
        mp[lane + 32 * j] = m;
    }

    if (lane == 0) {
        atomicAdd(&bs[0], a0);
        atomicAdd(&bs[1], a1);
        atomicAdd(&bs[2], a2);
    }
    __syncthreads();
    if (tid < NREL) atomicAdd(&g_s[tid], (double)bs[tid]);
}

// ---- kernel 2: TF32 GEMM  out[col][row] = relu( sum_k Xmix[row][k] * W[col][k] )
__global__ __launch_bounds__(256)
void gemm_kernel(const float* __restrict__ W, float* __restrict__ out) {
    __shared__ float As[128 * 20];   // [row][k], stride 20
    __shared__ float Bs[128 * 20];   // [col][k]
    __shared__ float Ts[32 * 132];   // transpose staging: [e_local][n_local]

    const int tid  = threadIdx.x;
    const int wid  = tid >> 5, lane = tid & 31;
    const int wm   = wid >> 2;   // 0..1
    const int wn   = wid & 3;    // 0..3
    const int g    = lane >> 2;  // 0..7
    const int tg   = lane & 3;   // 0..3

    const size_t rowBlk = (size_t)blockIdx.y * 128;
    const int    colBlk = blockIdx.x * 128;
    const float* Aptr = g_mix + rowBlk * FEAT;
    const float* Bp   = W + (size_t)colBlk * FEAT;

    const int r0 = tid >> 2;           // 0..63
    const int kq = (tid & 3) * 4;      // k quad offset

    {
        float4 a0v = *(const float4*)(Aptr + (size_t)r0 * FEAT + kq);
        float4 a1v = *(const float4*)(Aptr + (size_t)(r0 + 64) * FEAT + kq);
        float4 b0v = *(const float4*)(Bp   + (size_t)r0 * FEAT + kq);
        float4 b1v = *(const float4*)(Bp   + (size_t)(r0 + 64) * FEAT + kq);
        cvt4(&As[r0 * 20 + kq], a0v);  cvt4(&As[(r0 + 64) * 20 + kq], a1v);
        cvt4(&Bs[r0 * 20 + kq], b0v);  cvt4(&Bs[(r0 + 64) * 20 + kq], b1v);
    }
    __syncthreads();

    float acc[4][4][4];
    #pragma unroll
    for (int i = 0; i < 4; ++i)
        #pragma unroll
        for (int j = 0; j < 4; ++j)
            #pragma unroll
            for (int q = 0; q < 4; ++q) acc[i][j][q] = 0.f;

    #pragma unroll 1
    for (int t = 0; t < 32; ++t) {
        float4 na0, na1, nb0, nb1;
        if (t < 31) {
            int k0 = (t + 1) * 16;
            na0 = *(const float4*)(Aptr + (size_t)r0 * FEAT + k0 + kq);
            na1 = *(const float4*)(Aptr + (size_t)(r0 + 64) * FEAT + k0 + kq);
            nb0 = *(const float4*)(Bp   + (size_t)r0 * FEAT + k0 + kq);
            nb1 = *(const float4*)(Bp   + (size_t)(r0 + 64) * FEAT + k0 + kq);
        }

        #pragma unroll
        for (int kk = 0; kk < 2; ++kk) {
            unsigned af[4][4], bf[4][2];
            #pragma unroll
            for (int mt = 0; mt < 4; ++mt) {
                int rr = wm * 64 + mt * 16;
                af[mt][0] = __float_as_uint(As[(rr + g    ) * 20 + kk * 8 + tg]);
                af[mt][1] = __float_as_uint(As[(rr + g + 8) * 20 + kk * 8 + tg]);
                af[mt][2] = __float_as_uint(As[(rr + g    ) * 20 + kk * 8 + tg + 4]);
                af[mt][3] = __float_as_uint(As[(rr + g + 8) * 20 + kk * 8 + tg + 4]);
            }
            #pragma unroll
            for (int nt = 0; nt < 4; ++nt) {
                int cc = wn * 32 + nt * 8;
                bf[nt][0] = __float_as_uint(Bs[(cc + g) * 20 + kk * 8 + tg]);
                bf[nt][1] = __float_as_uint(Bs[(cc + g) * 20 + kk * 8 + tg + 4]);
            }
            #pragma unroll
            for (int mt = 0; mt < 4; ++mt)
                #pragma unroll
                for (int nt = 0; nt < 4; ++nt)
                    mma_tf32(acc[mt][nt], af[mt], bf[nt]);
        }

        if (t < 31) {
            __syncthreads();
            cvt4(&As[r0 * 20 + kq], na0);  cvt4(&As[(r0 + 64) * 20 + kq], na1);
            cvt4(&Bs[r0 * 20 + kq], nb0);  cvt4(&Bs[(r0 + 64) * 20 + kq], nb1);
            __syncthreads();
        }
    }

    // epilogue: relu + transpose -> out[e][n], 32-col chunks.
    // Each chunk holds 32 e-rows x 128 n-cols = 4096 floats; 256 threads
    // drain 4 float4 each (el = e-row, j*32 + f4i*4 = n offset).
    #pragma unroll 1
    for (int c = 0; c < 4; ++c) {
        __syncthreads();
        if (wn == c) {
            #pragma unroll
            for (int mt = 0; mt < 4; ++mt) {
                #pragma unroll
                for (int nt = 0; nt < 4; ++nt) {
                    int colL = nt * 8 + 2 * tg;
                    int rowL = wm * 64 + mt * 16 + g;
                    float q0 = acc[mt][nt][0], q1 = acc[mt][nt][1];
                    float q2 = acc[mt][nt][2], q3 = acc[mt][nt][3];
                    Ts[(colL    ) * 132 + rowL    ] = q0 > 0.f ? q0 : 0.f;
                    Ts[(colL + 1) * 132 + rowL    ] = q1 > 0.f ? q1 : 0.f;
                    Ts[(colL    ) * 132 + rowL + 8] = q2 > 0.f ? q2 : 0.f;
                    Ts[(colL + 1) * 132 + rowL + 8] = q3 > 0.f ? q3 : 0.f;
                }
            }
        }
        __syncthreads();
        int el  = tid >> 3;          // 0..31 : e row within chunk
        int f4i = tid & 7;           // 0..7
        size_t obase = (size_t)(colBlk + c * 32 + el) * NNODES + rowBlk;
        #pragma unroll
        for (int j = 0; j < 4; ++j) {
            float4 v = *(const float4*)&Ts[el * 132 + j * 32 + f4i * 4];
            *(float4*)&out[obase + j * 32 + f4i * 4] = v;
        }
    }
}

// ---- kernel 3: softmax over 3 relation sums -> tail of output ----
__global__ void attout_kernel(float* __restrict__ out) {
    double s0 = g_s[0], s1 = g_s[1], s2 = g_s[2];
    double m = fmax(s0, fmax(s1, s2));
    double e0 = exp(s0 - m), e1 = exp(s1 - m), e2 = exp(s2 - m);
    double inv = 1.0 / (e0 + e1 + e2);
    size_t base = (size_t)EMB * NNODES;
    out[base + 0] = (float)(e0 * inv);
    out[base + 1] = (float)(e1 * inv);
    out[base + 2] = (float)(e2 * inv);
}

extern "C" void kernel_launch(void* const* d_in, const int* in_sizes, int n_in,
                              void* d_out, int out_size) {
    const float* selfF  = (const float*)d_in[0];
    const float* neighF = (const float*)d_in[1];
    const float* W      = (const float*)d_in[2];
    const float* a      = (const float*)d_in[3];
    float* out = (float*)d_out;

    prep_kernel<<<4, 128>>>(W, a);

    mix_kernel<<<NNODES / 8, 256>>>(selfF, neighF);

    dim3 ggrid(EMB / 128, NNODES / 128);   // (4, 512)
    gemm_kernel<<<ggrid, 256>>>(W, out);

    attout_kernel<<<1, 1>>>(out);
}

// round 5
// speedup vs baseline: 3.9047x; 1.3267x over previous
#include <cuda_runtime.h>
#include <cuda_fp16.h>
#include <cstdint>
#include <math.h>

#define NREL   3
#define NNODES 65536
#define FEAT   512
#define EMB    512
#define BK     32            // k halves per chunk
#define NCHUNK (FEAT/BK)     // 16

// ---- scratch (static device globals; no allocations allowed) ----
__device__ __half  g_mixh[(size_t)NNODES * FEAT];  // 67 MB fp16 mixed features
__device__ __half  g_Wh[(size_t)EMB * FEAT];       // fp16 weight copy
__device__ float   g_u[2*EMB];
__device__ double  g_s[NREL];

__device__ __forceinline__ void mma_f16(float c[4], const unsigned a[4], const unsigned b[2]) {
    asm volatile(
        "mma.sync.aligned.m16n8k16.row.col.f32.f16.f16.f32 "
        "{%0,%1,%2,%3}, {%4,%5,%6,%7}, {%8,%9}, {%0,%1,%2,%3};\n"
        : "+f"(c[0]), "+f"(c[1]), "+f"(c[2]), "+f"(c[3])
        : "r"(a[0]), "r"(a[1]), "r"(a[2]), "r"(a[3]), "r"(b[0]), "r"(b[1]));
}

// ---- kernel 0a: u_c = W^T a_c, u_n = W^T a_n; zero relation sums ----
__global__ void prep_kernel(const float* __restrict__ W, const float* __restrict__ a) {
    int f = blockIdx.x * blockDim.x + threadIdx.x;   // 0..511
    float sc = 0.f, sn = 0.f;
    for (int e = 0; e < EMB; ++e) {
        float w = W[(size_t)e * FEAT + f];
        sc += w * a[e];
        sn += w * a[EMB + e];
    }
    g_u[f]       = sc;
    g_u[EMB + f] = sn;
    if (f < NREL) g_s[f] = 0.0;
}

// ---- kernel 0b: W -> fp16 ----
__global__ void wconv_kernel(const float* __restrict__ W) {
    int i = blockIdx.x * blockDim.x + threadIdx.x;   // float4 index
    float4 v = ((const float4*)W)[i];
    __half2 h0 = __floats2half2_rn(v.x, v.y);
    __half2 h1 = __floats2half2_rn(v.z, v.w);
    uint2 p;
    p.x = *(unsigned*)&h0;  p.y = *(unsigned*)&h1;
    ((uint2*)g_Wh)[i] = p;
}

// ---- kernel 1: per-node attention + feature mix (one warp per node), fp16 out ----
__global__ __launch_bounds__(256)
void mix_kernel(const float* __restrict__ selfF, const float* __restrict__ neighF) {
    __shared__ float bs[NREL];
    const int tid  = threadIdx.x;
    const int lane = tid & 31;
    const int n    = blockIdx.x * 8 + (tid >> 5);

    if (tid < NREL) bs[tid] = 0.f;
    __syncthreads();

    const float4* sp  = (const float4*)(selfF + (size_t)n * FEAT);
    const float4* np0 = (const float4*)(neighF + ((size_t)0 * NNODES + n) * FEAT);
    const float4* np1 = (const float4*)(neighF + ((size_t)1 * NNODES + n) * FEAT);
    const float4* np2 = (const float4*)(neighF + ((size_t)2 * NNODES + n) * FEAT);
    const float4* ucp = (const float4*)(g_u);
    const float4* unp = (const float4*)(g_u + EMB);

    float4 s[4], n0[4], n1[4], n2[4], uc[4], un[4];
    #pragma unroll
    for (int j = 0; j < 4; ++j) {
        int idx = lane + 32 * j;
        s[j]  = sp[idx];  n0[j] = np0[idx];  n1[j] = np1[idx];  n2[j] = np2[idx];
        uc[j] = ucp[idx]; un[j] = unp[idx];
    }

    float ec = 0.f, e0 = 0.f, e1 = 0.f, e2 = 0.f;
    #pragma unroll
    for (int j = 0; j < 4; ++j) {
        ec += s[j].x*uc[j].x + s[j].y*uc[j].y + s[j].z*uc[j].z + s[j].w*uc[j].w;
        e0 += n0[j].x*un[j].x + n0[j].y*un[j].y + n0[j].z*un[j].z + n0[j].w*un[j].w;
        e1 += n1[j].x*un[j].x + n1[j].y*un[j].y + n1[j].z*un[j].z + n1[j].w*un[j].w;
        e2 += n2[j].x*un[j].x + n2[j].y*un[j].y + n2[j].z*un[j].z + n2[j].w*un[j].w;
    }
    #pragma unroll
    for (int o = 16; o; o >>= 1) {
        ec += __shfl_xor_sync(0xffffffffu, ec, o);
        e0 += __shfl_xor_sync(0xffffffffu, e0, o);
        e1 += __shfl_xor_sync(0xffffffffu, e1, o);
        e2 += __shfl_xor_sync(0xffffffffu, e2, o);
    }

    float v0 = ec + e0, v1 = ec + e1, v2 = ec + e2;
    v0 = v0 > 0.f ? v0 : 0.2f * v0;
    v1 = v1 > 0.f ? v1 : 0.2f * v1;
    v2 = v2 > 0.f ? v2 : 0.2f * v2;
    float mx = fmaxf(v0, fmaxf(v1, v2));
    float x0 = expf(v0 - mx), x1 = expf(v1 - mx), x2 = expf(v2 - mx);
    float inv = 1.f / (x0 + x1 + x2);
    float a0 = x0 * inv, a1 = x1 * inv, a2 = x2 * inv;

    uint2* mp = (uint2*)(g_mixh + (size_t)n * FEAT);
    #pragma unroll
    for (int j = 0; j < 4; ++j) {
        float4 m;
        m.x = s[j].x + a0*n0[j].x + a1*n1[j].x + a2*n2[j].x;
        m.y = s[j].y + a0*n0[j].y + a1*n1[j].y + a2*n2[j].y;
        m.z = s[j].z + a0*n0[j].z + a1*n1[j].z + a2*n2[j].z;
        m.w = s[j].w + a0*n0[j].w + a1*n1[j].w + a2*n2[j].w;
        __half2 h0 = __floats2half2_rn(m.x, m.y);
        __half2 h1 = __floats2half2_rn(m.z, m.w);
        uint2 p;
        p.x = *(unsigned*)&h0;  p.y = *(unsigned*)&h1;
        mp[lane + 32 * j] = p;
    }

    if (lane == 0) { atomicAdd(&bs[0], a0); atomicAdd(&bs[1], a1); atomicAdd(&bs[2], a2); }
    __syncthreads();
    if (tid < NREL) atomicAdd(&g_s[tid], (double)bs[tid]);
}

// ---- kernel 2: fp16 mma.sync GEMM  out[col][row] = relu( sum_k mix[row][k] * W[col][k] )
//      A rows = nodes (128), B rows = e (128), BK=32 halves; 8 warps 2m x 4n,
//      warp tile 64x32, m16n8k16. Epilogue: relu + smem transpose -> out[e][n].
__global__ __launch_bounds__(256)
void gemm_kernel(float* __restrict__ out) {
    __shared__ __align__(16) __half As[128 * 40];   // [row][k], stride 40 halves
    __shared__ __align__(16) __half Bs[128 * 40];
    __shared__ float Ts[32 * 132];

    const int tid  = threadIdx.x;
    const int wid  = tid >> 5, lane = tid & 31;
    const int wm   = wid >> 2;   // 0..1
    const int wn   = wid & 3;    // 0..3
    const int g    = lane >> 2;  // 0..7
    const int tg   = lane & 3;   // 0..3

    const size_t rowBlk = (size_t)blockIdx.y * 128;   // nodes
    const int    colBlk = blockIdx.x * 128;           // embed
    const __half* Aptr = g_mixh + rowBlk * FEAT;
    const __half* Bp   = g_Wh + (size_t)colBlk * FEAT;

    const int r0  = tid >> 2;          // 0..63
    const int kq8 = (tid & 3) * 8;     // half offset within chunk

    // prologue: chunk 0 -> smem (raw fp16 uint4 copies)
    {
        uint4 a0 = *(const uint4*)(Aptr + (size_t)r0 * FEAT + kq8);
        uint4 a1 = *(const uint4*)(Aptr + (size_t)(r0 + 64) * FEAT + kq8);
        uint4 b0 = *(const uint4*)(Bp   + (size_t)r0 * FEAT + kq8);
        uint4 b1 = *(const uint4*)(Bp   + (size_t)(r0 + 64) * FEAT + kq8);
        *(uint4*)&As[r0 * 40 + kq8]        = a0;
        *(uint4*)&As[(r0 + 64) * 40 + kq8] = a1;
        *(uint4*)&Bs[r0 * 40 + kq8]        = b0;
        *(uint4*)&Bs[(r0 + 64) * 40 + kq8] = b1;
    }
    __syncthreads();

    float acc[4][4][4];
    #pragma unroll
    for (int i = 0; i < 4; ++i)
        #pragma unroll
        for (int j = 0; j < 4; ++j)
            #pragma unroll
            for (int q = 0; q < 4; ++q) acc[i][j][q] = 0.f;

    #pragma unroll 1
    for (int t = 0; t < NCHUNK; ++t) {
        uint4 na0, na1, nb0, nb1;
        if (t < NCHUNK - 1) {
            int k0 = (t + 1) * BK;
            na0 = *(const uint4*)(Aptr + (size_t)r0 * FEAT + k0 + kq8);
            na1 = *(const uint4*)(Aptr + (size_t)(r0 + 64) * FEAT + k0 + kq8);
            nb0 = *(const uint4*)(Bp   + (size_t)r0 * FEAT + k0 + kq8);
            nb1 = *(const uint4*)(Bp   + (size_t)(r0 + 64) * FEAT + k0 + kq8);
        }

        #pragma unroll
        for (int kk = 0; kk < 2; ++kk) {
            const int kb = kk * 16 + 2 * tg;
            unsigned af[4][4], bf[4][2];
            #pragma unroll
            for (int mt = 0; mt < 4; ++mt) {
                int rr = wm * 64 + mt * 16;
                af[mt][0] = *(const unsigned*)&As[(rr + g    ) * 40 + kb];
                af[mt][1] = *(const unsigned*)&As[(rr + g + 8) * 40 + kb];
                af[mt][2] = *(const unsigned*)&As[(rr + g    ) * 40 + kb + 8];
                af[mt][3] = *(const unsigned*)&As[(rr + g + 8) * 40 + kb + 8];
            }
            #pragma unroll
            for (int nt = 0; nt < 4; ++nt) {
                int cc = wn * 32 + nt * 8;
                bf[nt][0] = *(const unsigned*)&Bs[(cc + g) * 40 + kb];
                bf[nt][1] = *(const unsigned*)&Bs[(cc + g) * 40 + kb + 8];
            }
            #pragma unroll
            for (int mt = 0; mt < 4; ++mt)
                #pragma unroll
                for (int nt = 0; nt < 4; ++nt)
                    mma_f16(acc[mt][nt], af[mt], bf[nt]);
        }

        if (t < NCHUNK - 1) {
            __syncthreads();
            *(uint4*)&As[r0 * 40 + kq8]        = na0;
            *(uint4*)&As[(r0 + 64) * 40 + kq8] = na1;
            *(uint4*)&Bs[r0 * 40 + kq8]        = nb0;
            *(uint4*)&Bs[(r0 + 64) * 40 + kq8] = nb1;
            __syncthreads();
        }
    }

    // epilogue: relu + transpose -> out[e][n], four 32-e-row chunks
    #pragma unroll 1
    for (int c = 0; c < 4; ++c) {
        __syncthreads();
        if (wn == c) {
            #pragma unroll
            for (int mt = 0; mt < 4; ++mt) {
                #pragma unroll
                for (int nt = 0; nt < 4; ++nt) {
                    int colL = nt * 8 + 2 * tg;
                    int rowL = wm * 64 + mt * 16 + g;
                    float q0 = acc[mt][nt][0], q1 = acc[mt][nt][1];
                    float q2 = acc[mt][nt][2], q3 = acc[mt][nt][3];
                    Ts[(colL    ) * 132 + rowL    ] = q0 > 0.f ? q0 : 0.f;
                    Ts[(colL + 1) * 132 + rowL    ] = q1 > 0.f ? q1 : 0.f;
                    Ts[(colL    ) * 132 + rowL + 8] = q2 > 0.f ? q2 : 0.f;
                    Ts[(colL + 1) * 132 + rowL + 8] = q3 > 0.f ? q3 : 0.f;
                }
            }
        }
        __syncthreads();
        int el  = tid >> 3;          // 0..31
        int f4i = tid & 7;           // 0..7
        size_t obase = (size_t)(colBlk + c * 32 + el) * NNODES + rowBlk;
        #pragma unroll
        for (int j = 0; j < 4; ++j) {
            float4 v = *(const float4*)&Ts[el * 132 + j * 32 + f4i * 4];
            *(float4*)&out[obase + j * 32 + f4i * 4] = v;
        }
    }
}

// ---- kernel 3: softmax over 3 relation sums -> tail of output ----
__global__ void attout_kernel(float* __restrict__ out) {
    double s0 = g_s[0], s1 = g_s[1], s2 = g_s[2];
    double m = fmax(s0, fmax(s1, s2));
    double e0 = exp(s0 - m), e1 = exp(s1 - m), e2 = exp(s2 - m);
    double inv = 1.0 / (e0 + e1 + e2);
    size_t base = (size_t)EMB * NNODES;
    out[base + 0] = (float)(e0 * inv);
    out[base + 1] = (float)(e1 * inv);
    out[base + 2] = (float)(e2 * inv);
}

extern "C" void kernel_launch(void* const* d_in, const int* in_sizes, int n_in,
                              void* d_out, int out_size) {
    const float* selfF  = (const float*)d_in[0];
    const float* neighF = (const float*)d_in[1];
    const float* W      = (const float*)d_in[2];
    const float* a      = (const float*)d_in[3];
    float* out = (float*)d_out;

    prep_kernel<<<4, 128>>>(W, a);
    wconv_kernel<<<256, 256>>>(W);          // 65536 float4 groups
    mix_kernel<<<NNODES / 8, 256>>>(selfF, neighF);

    dim3 ggrid(EMB / 128, NNODES / 128);    // (4, 512)
    gemm_kernel<<<ggrid, 256>>>(out);

    attout_kernel<<<1, 1>>>(out);
}

// round 6
// speedup vs baseline: 4.4428x; 1.1378x over previous
#include <cuda_runtime.h>
#include <cuda_fp16.h>
#include <cstdint>
#include <math.h>

#define NREL   3
#define NNODES 65536
#define FEAT   512
#define EMB    512
#define BK     32            // k halves per chunk
#define NCHUNK (FEAT/BK)     // 16

// ---- scratch (static device globals; no allocations allowed) ----
__device__ __half  g_mixh[(size_t)NNODES * FEAT];  // 67 MB fp16 mixed features
__device__ __half  g_Wh[(size_t)EMB * FEAT];       // fp16 weight copy
__device__ float   g_u[2*EMB];
__device__ float   g_up[64 * 1024];                // prep partials
__device__ double  g_s[NREL];

__device__ __forceinline__ uint32_t smem_u32(const void* p) {
    uint32_t a;
    asm("{ .reg .u64 t; cvta.to.shared.u64 t, %1; cvt.u32.u64 %0, t; }" : "=r"(a) : "l"(p));
    return a;
}

__device__ __forceinline__ void mma_f16(float c[4], const unsigned a[4], const unsigned b[2]) {
    asm volatile(
        "mma.sync.aligned.m16n8k16.row.col.f32.f16.f16.f32 "
        "{%0,%1,%2,%3}, {%4,%5,%6,%7}, {%8,%9}, {%0,%1,%2,%3};\n"
        : "+f"(c[0]), "+f"(c[1]), "+f"(c[2]), "+f"(c[3])
        : "r"(a[0]), "r"(a[1]), "r"(a[2]), "r"(a[3]), "r"(b[0]), "r"(b[1]));
}

__device__ __forceinline__ void ldsm4(unsigned r[4], uint32_t addr) {
    asm volatile("ldmatrix.sync.aligned.m8n8.x4.shared.b16 {%0,%1,%2,%3}, [%4];"
        : "=r"(r[0]), "=r"(r[1]), "=r"(r[2]), "=r"(r[3]) : "r"(addr));
}

// ---- kernel 0a: partial u sums over 8 e-rows per block (deterministic 2-stage) ----
__global__ __launch_bounds__(512)
void prep1_kernel(const float* __restrict__ W, const float* __restrict__ a) {
    int f = threadIdx.x;          // 0..511
    int b = blockIdx.x;           // 0..63
    int e0 = b * 8;
    float sc = 0.f, sn = 0.f;
    #pragma unroll
    for (int j = 0; j < 8; ++j) {
        float w = W[(size_t)(e0 + j) * FEAT + f];
        sc += w * a[e0 + j];
        sn += w * a[EMB + e0 + j];
    }
    g_up[b * 1024 + f]       = sc;
    g_up[b * 1024 + 512 + f] = sn;
}

__global__ void prep2_kernel() {
    int i = blockIdx.x * 256 + threadIdx.x;   // 0..1023
    float s = 0.f;
    #pragma unroll
    for (int b = 0; b < 64; ++b) s += g_up[b * 1024 + i];
    g_u[i] = s;
    if (i < NREL) g_s[i] = 0.0;
}

// ---- kernel 0b: W -> fp16 ----
__global__ void wconv_kernel(const float* __restrict__ W) {
    int i = blockIdx.x * blockDim.x + threadIdx.x;   // float4 index
    float4 v = ((const float4*)W)[i];
    __half2 h0 = __floats2half2_rn(v.x, v.y);
    __half2 h1 = __floats2half2_rn(v.z, v.w);
    uint2 p;
    p.x = *(unsigned*)&h0;  p.y = *(unsigned*)&h1;
    ((uint2*)g_Wh)[i] = p;
}

// ---- kernel 1: per-node attention + feature mix (one warp per node), fp16 out ----
__global__ __launch_bounds__(256)
void mix_kernel(const float* __restrict__ selfF, const float* __restrict__ neighF) {
    __shared__ float bs[NREL];
    const int tid  = threadIdx.x;
    const int lane = tid & 31;
    const int n    = blockIdx.x * 8 + (tid >> 5);

    if (tid < NREL) bs[tid] = 0.f;
    __syncthreads();

    const float4* sp  = (const float4*)(selfF + (size_t)n * FEAT);
    const float4* np0 = (const float4*)(neighF + ((size_t)0 * NNODES + n) * FEAT);
    const float4* np1 = (const float4*)(neighF + ((size_t)1 * NNODES + n) * FEAT);
    const float4* np2 = (const float4*)(neighF + ((size_t)2 * NNODES + n) * FEAT);
    const float4* ucp = (const float4*)(g_u);
    const float4* unp = (const float4*)(g_u + EMB);

    float4 s[4], n0[4], n1[4], n2[4], uc[4], un[4];
    #pragma unroll
    for (int j = 0; j < 4; ++j) {
        int idx = lane + 32 * j;
        s[j]  = sp[idx];  n0[j] = np0[idx];  n1[j] = np1[idx];  n2[j] = np2[idx];
        uc[j] = ucp[idx]; un[j] = unp[idx];
    }

    float ec = 0.f, e0 = 0.f, e1 = 0.f, e2 = 0.f;
    #pragma unroll
    for (int j = 0; j < 4; ++j) {
        ec += s[j].x*uc[j].x + s[j].y*uc[j].y + s[j].z*uc[j].z + s[j].w*uc[j].w;
        e0 += n0[j].x*un[j].x + n0[j].y*un[j].y + n0[j].z*un[j].z + n0[j].w*un[j].w;
        e1 += n1[j].x*un[j].x + n1[j].y*un[j].y + n1[j].z*un[j].z + n1[j].w*un[j].w;
        e2 += n2[j].x*un[j].x + n2[j].y*un[j].y + n2[j].z*un[j].z + n2[j].w*un[j].w;
    }
    #pragma unroll
    for (int o = 16; o; o >>= 1) {
        ec += __shfl_xor_sync(0xffffffffu, ec, o);
        e0 += __shfl_xor_sync(0xffffffffu, e0, o);
        e1 += __shfl_xor_sync(0xffffffffu, e1, o);
        e2 += __shfl_xor_sync(0xffffffffu, e2, o);
    }

    float v0 = ec + e0, v1 = ec + e1, v2 = ec + e2;
    v0 = v0 > 0.f ? v0 : 0.2f * v0;
    v1 = v1 > 0.f ? v1 : 0.2f * v1;
    v2 = v2 > 0.f ? v2 : 0.2f * v2;
    float mx = fmaxf(v0, fmaxf(v1, v2));
    float x0 = expf(v0 - mx), x1 = expf(v1 - mx), x2 = expf(v2 - mx);
    float inv = 1.f / (x0 + x1 + x2);
    float a0 = x0 * inv, a1 = x1 * inv, a2 = x2 * inv;

    uint2* mp = (uint2*)(g_mixh + (size_t)n * FEAT);
    #pragma unroll
    for (int j = 0; j < 4; ++j) {
        float4 m;
        m.x = s[j].x + a0*n0[j].x + a1*n1[j].x + a2*n2[j].x;
        m.y = s[j].y + a0*n0[j].y + a1*n1[j].y + a2*n2[j].y;
        m.z = s[j].z + a0*n0[j].z + a1*n1[j].z + a2*n2[j].z;
        m.w = s[j].w + a0*n0[j].w + a1*n1[j].w + a2*n2[j].w;
        __half2 h0 = __floats2half2_rn(m.x, m.y);
        __half2 h1 = __floats2half2_rn(m.z, m.w);
        uint2 p;
        p.x = *(unsigned*)&h0;  p.y = *(unsigned*)&h1;
        mp[lane + 32 * j] = p;
    }

    if (lane == 0) { atomicAdd(&bs[0], a0); atomicAdd(&bs[1], a1); atomicAdd(&bs[2], a2); }
    __syncthreads();
    if (tid < NREL) atomicAdd(&g_s[tid], (double)bs[tid]);
}

// ---- kernel 2: fp16 mma.sync GEMM with ldmatrix + 2-stage double buffer ----
// out[col][row] = relu( sum_k mix[row][k] * W[col][k] ); 8 warps 2m x 4n.
// Smem layout (40960 B): A0[0,10240) B0[10240,20480) A1[20480,30720) B1[30720,40960)
// Epilogue transpose buffer Ts aliases the same smem.
__global__ __launch_bounds__(256)
void gemm_kernel(float* __restrict__ out) {
    __shared__ __align__(16) char sm[40960];
    const int tid  = threadIdx.x;
    const int wid  = tid >> 5, lane = tid & 31;
    const int wm   = wid >> 2;   // 0..1
    const int wn   = wid & 3;    // 0..3
    const int g    = lane >> 2;
    const int tg   = lane & 3;

    const size_t rowBlk = (size_t)blockIdx.y * 128;   // nodes
    const int    colBlk = blockIdx.x * 128;           // embed
    const __half* Aptr = g_mixh + rowBlk * FEAT;
    const __half* Bp   = g_Wh + (size_t)colBlk * FEAT;

    const uint32_t base = smem_u32(sm);
    char* const pA[2] = { sm,          sm + 20480 };
    char* const pB[2] = { sm + 10240,  sm + 30720 };
    const uint32_t uA[2] = { base,          base + 20480 };
    const uint32_t uB[2] = { base + 10240,  base + 30720 };

    const int r0  = tid >> 2;          // 0..63
    const int kq8 = (tid & 3) * 8;     // half offset within chunk
    const uint32_t st0 = (uint32_t)(r0 * 40 + kq8) * 2;       // store offset row r0
    const uint32_t st1 = st0 + 64 * 40 * 2;                   // row r0+64

    // ldmatrix per-lane byte offsets
    const uint32_t laneA = (uint32_t)(((lane & 15) * 40 + (lane >> 4) * 8) * 2);
    const uint32_t laneB = (uint32_t)((((lane & 7) + ((lane >> 4) << 3)) * 40
                                       + (((lane >> 3) & 1) << 3)) * 2);

    // prologue: chunk 0 -> stage 0
    {
        uint4 a0 = *(const uint4*)(Aptr + (size_t)r0 * FEAT + kq8);
        uint4 a1 = *(const uint4*)(Aptr + (size_t)(r0 + 64) * FEAT + kq8);
        uint4 b0 = *(const uint4*)(Bp   + (size_t)r0 * FEAT + kq8);
        uint4 b1 = *(const uint4*)(Bp   + (size_t)(r0 + 64) * FEAT + kq8);
        *(uint4*)(pA[0] + st0) = a0;  *(uint4*)(pA[0] + st1) = a1;
        *(uint4*)(pB[0] + st0) = b0;  *(uint4*)(pB[0] + st1) = b1;
    }
    __syncthreads();

    float acc[4][4][4];
    #pragma unroll
    for (int i = 0; i < 4; ++i)
        #pragma unroll
        for (int j = 0; j < 4; ++j)
            #pragma unroll
            for (int q = 0; q < 4; ++q) acc[i][j][q] = 0.f;

    #pragma unroll 1
    for (int t = 0; t < NCHUNK; ++t) {
        const int st = t & 1;
        uint4 na0, na1, nb0, nb1;
        if (t < NCHUNK - 1) {
            int k0 = (t + 1) * BK;
            na0 = *(const uint4*)(Aptr + (size_t)r0 * FEAT + k0 + kq8);
            na1 = *(const uint4*)(Aptr + (size_t)(r0 + 64) * FEAT + k0 + kq8);
            nb0 = *(const uint4*)(Bp   + (size_t)r0 * FEAT + k0 + kq8);
            nb1 = *(const uint4*)(Bp   + (size_t)(r0 + 64) * FEAT + k0 + kq8);
        }

        #pragma unroll
        for (int kk = 0; kk < 2; ++kk) {
            unsigned af[4][4], bf[4][2];
            #pragma unroll
            for (int mt = 0; mt < 4; ++mt) {
                uint32_t addr = uA[st] + laneA
                              + (uint32_t)((((wm * 64 + mt * 16) * 40) + kk * 16) * 2);
                ldsm4(af[mt], addr);
            }
            #pragma unroll
            for (int p = 0; p < 2; ++p) {
                unsigned r[4];
                uint32_t addr = uB[st] + laneB
                              + (uint32_t)((((wn * 32 + p * 16) * 40) + kk * 16) * 2);
                ldsm4(r, addr);
                bf[2*p  ][0] = r[0];  bf[2*p  ][1] = r[1];
                bf[2*p+1][0] = r[2];  bf[2*p+1][1] = r[3];
            }
            #pragma unroll
            for (int mt = 0; mt < 4; ++mt)
                #pragma unroll
                for (int nt = 0; nt < 4; ++nt)
                    mma_f16(acc[mt][nt], af[mt], bf[nt]);
        }

        if (t < NCHUNK - 1) {
            const int ns = st ^ 1;
            *(uint4*)(pA[ns] + st0) = na0;  *(uint4*)(pA[ns] + st1) = na1;
            *(uint4*)(pB[ns] + st0) = nb0;  *(uint4*)(pB[ns] + st1) = nb1;
            __syncthreads();
        }
    }

    // epilogue: relu + transpose -> out[e][n]; Ts aliases the smem buffers
    float* Ts = (float*)sm;   // 32 x 132
    #pragma unroll 1
    for (int c = 0; c < 4; ++c) {
        __syncthreads();
        if (wn == c) {
            #pragma unroll
            for (int mt = 0; mt < 4; ++mt) {
                #pragma unroll
                for (int nt = 0; nt < 4; ++nt) {
                    int colL = nt * 8 + 2 * tg;
                    int rowL = wm * 64 + mt * 16 + g;
                    float q0 = acc[mt][nt][0], q1 = acc[mt][nt][1];
                    float q2 = acc[mt][nt][2], q3 = acc[mt][nt][3];
                    Ts[(colL    ) * 132 + rowL    ] = q0 > 0.f ? q0 : 0.f;
                    Ts[(colL + 1) * 132 + rowL    ] = q1 > 0.f ? q1 : 0.f;
                    Ts[(colL    ) * 132 + rowL + 8] = q2 > 0.f ? q2 : 0.f;
                    Ts[(colL + 1) * 132 + rowL + 8] = q3 > 0.f ? q3 : 0.f;
                }
            }
        }
        __syncthreads();
        int el  = tid >> 3;          // 0..31
        int f4i = tid & 7;           // 0..7
        size_t obase = (size_t)(colBlk + c * 32 + el) * NNODES + rowBlk;
        #pragma unroll
        for (int j = 0; j < 4; ++j) {
            float4 v = *(const float4*)&Ts[el * 132 + j * 32 + f4i * 4];
            *(float4*)&out[obase + j * 32 + f4i * 4] = v;
        }
    }

    // fused tail: softmax over 3 relation sums
    if (blockIdx.x == 0 && blockIdx.y == 0 && tid == 0) {
        double s0 = g_s[0], s1 = g_s[1], s2 = g_s[2];
        double m = fmax(s0, fmax(s1, s2));
        double e0 = exp(s0 - m), e1 = exp(s1 - m), e2 = exp(s2 - m);
        double inv = 1.0 / (e0 + e1 + e2);
        size_t obase2 = (size_t)EMB * NNODES;
        out[obase2 + 0] = (float)(e0 * inv);
        out[obase2 + 1] = (float)(e1 * inv);
        out[obase2 + 2] = (float)(e2 * inv);
    }
}

extern "C" void kernel_launch(void* const* d_in, const int* in_sizes, int n_in,
                              void* d_out, int out_size) {
    const float* selfF  = (const float*)d_in[0];
    const float* neighF = (const float*)d_in[1];
    const float* W      = (const float*)d_in[2];
    const float* a      = (const float*)d_in[3];
    float* out = (float*)d_out;

    prep1_kernel<<<64, 512>>>(W, a);
    prep2_kernel<<<4, 256>>>();
    wconv_kernel<<<256, 256>>>(W);
    mix_kernel<<<NNODES / 8, 256>>>(selfF, neighF);

    dim3 ggrid(EMB / 128, NNODES / 128);    // (4, 512)
    gemm_kernel<<<ggrid, 256>>>(out);
}

// round 7
// speedup vs baseline: 4.8802x; 1.0985x over previous
#include <cuda_runtime.h>
#include <cuda_fp16.h>
#include <cstdint>
#include <math.h>

#define NREL   3
#define NNODES 65536
#define FEAT   512
#define EMB    512
#define BK     32            // k halves per chunk
#define NCHUNK (FEAT/BK)     // 16

// ---- scratch (static device globals; no allocations allowed) ----
__device__ __half  g_mixh[(size_t)NNODES * FEAT];  // 67 MB fp16 mixed features
__device__ __half  g_Wh[(size_t)EMB * FEAT];       // fp16 weight copy
__device__ float   g_u[2*EMB];
__device__ float   g_up[64 * 1024];                // prep partials
__device__ double  g_s[NREL];

__device__ __forceinline__ uint32_t smem_u32(const void* p) {
    uint32_t a;
    asm("{ .reg .u64 t; cvta.to.shared.u64 t, %1; cvt.u32.u64 %0, t; }" : "=r"(a) : "l"(p));
    return a;
}

__device__ __forceinline__ void mma_f16(float c[4], const unsigned a[4], const unsigned b[2]) {
    asm volatile(
        "mma.sync.aligned.m16n8k16.row.col.f32.f16.f16.f32 "
        "{%0,%1,%2,%3}, {%4,%5,%6,%7}, {%8,%9}, {%0,%1,%2,%3};\n"
        : "+f"(c[0]), "+f"(c[1]), "+f"(c[2]), "+f"(c[3])
        : "r"(a[0]), "r"(a[1]), "r"(a[2]), "r"(a[3]), "r"(b[0]), "r"(b[1]));
}

__device__ __forceinline__ void ldsm4(unsigned r[4], uint32_t addr) {
    asm volatile("ldmatrix.sync.aligned.m8n8.x4.shared.b16 {%0,%1,%2,%3}, [%4];"
        : "=r"(r[0]), "=r"(r[1]), "=r"(r[2]), "=r"(r[3]) : "r"(addr));
}

// ---- kernel 0a: W -> fp16 + partial u sums (8 e-rows per block) ----
__global__ __launch_bounds__(512)
void wprep_kernel(const float* __restrict__ W, const float* __restrict__ a) {
    int f = threadIdx.x;          // 0..511
    int b = blockIdx.x;           // 0..63
    int e0 = b * 8;
    float sc = 0.f, sn = 0.f;
    #pragma unroll
    for (int j = 0; j < 8; ++j) {
        float w = W[(size_t)(e0 + j) * FEAT + f];
        g_Wh[(size_t)(e0 + j) * FEAT + f] = __float2half_rn(w);
        sc += w * a[e0 + j];
        sn += w * a[EMB + e0 + j];
    }
    g_up[b * 1024 + f]       = sc;
    g_up[b * 1024 + 512 + f] = sn;
}

__global__ void prep2_kernel() {
    int i = blockIdx.x * 256 + threadIdx.x;   // 0..1023
    float s = 0.f;
    #pragma unroll
    for (int b = 0; b < 64; ++b) s += g_up[b * 1024 + i];
    g_u[i] = s;
    if (i < NREL) g_s[i] = 0.0;
}

// ---- kernel 1: per-node attention + feature mix.
//      2 warps per node (half feature-dim each), 4 nodes per 256-thread block.
//      u vectors staged in smem; low regs -> high occupancy -> DRAM roofline. ----
__global__ __launch_bounds__(256, 5)
void mix_kernel(const float* __restrict__ selfF, const float* __restrict__ neighF) {
    __shared__ float us[2 * EMB];        // uc | un
    __shared__ float dots[4][2][4];      // [node_local][half][ec,e0,e1,e2]
    __shared__ float bs[NREL];

    const int tid  = threadIdx.x;
    const int lane = tid & 31;
    const int wid  = tid >> 5;           // 0..7
    const int nl   = wid >> 1;           // node local 0..3
    const int half = wid & 1;            // feature half
    const int n    = blockIdx.x * 4 + nl;

    // stage u into smem: 256 float4, one per thread
    ((float4*)us)[tid] = ((const float4*)g_u)[tid];
    if (tid < NREL) bs[tid] = 0.f;
    __syncthreads();

    const float4* sp  = (const float4*)(selfF + (size_t)n * FEAT);
    const float4* np0 = (const float4*)(neighF + ((size_t)0 * NNODES + n) * FEAT);
    const float4* np1 = (const float4*)(neighF + ((size_t)1 * NNODES + n) * FEAT);
    const float4* np2 = (const float4*)(neighF + ((size_t)2 * NNODES + n) * FEAT);

    // each warp covers float4 indices half*64 + lane + 32*j, j=0,1
    float4 s[2], n0[2], n1[2], n2[2];
    #pragma unroll
    for (int j = 0; j < 2; ++j) {
        int idx = half * 64 + lane + 32 * j;
        s[j]  = sp[idx];
        n0[j] = np0[idx];
        n1[j] = np1[idx];
        n2[j] = np2[idx];
    }

    float ec = 0.f, e0 = 0.f, e1 = 0.f, e2 = 0.f;
    #pragma unroll
    for (int j = 0; j < 2; ++j) {
        int idx = half * 64 + lane + 32 * j;
        float4 uc = ((const float4*)us)[idx];
        float4 un = ((const float4*)us)[128 + idx];
        ec += s[j].x*uc.x + s[j].y*uc.y + s[j].z*uc.z + s[j].w*uc.w;
        e0 += n0[j].x*un.x + n0[j].y*un.y + n0[j].z*un.z + n0[j].w*un.w;
        e1 += n1[j].x*un.x + n1[j].y*un.y + n1[j].z*un.z + n1[j].w*un.w;
        e2 += n2[j].x*un.x + n2[j].y*un.y + n2[j].z*un.z + n2[j].w*un.w;
    }
    #pragma unroll
    for (int o = 16; o; o >>= 1) {
        ec += __shfl_xor_sync(0xffffffffu, ec, o);
        e0 += __shfl_xor_sync(0xffffffffu, e0, o);
        e1 += __shfl_xor_sync(0xffffffffu, e1, o);
        e2 += __shfl_xor_sync(0xffffffffu, e2, o);
    }
    if (lane == 0) {
        dots[nl][half][0] = ec;
        dots[nl][half][1] = e0;
        dots[nl][half][2] = e1;
        dots[nl][half][3] = e2;
    }
    __syncthreads();

    // combine halves (all lanes compute identically; order fixed -> deterministic)
    float fec = dots[nl][0][0] + dots[nl][1][0];
    float fe0 = dots[nl][0][1] + dots[nl][1][1];
    float fe1 = dots[nl][0][2] + dots[nl][1][2];
    float fe2 = dots[nl][0][3] + dots[nl][1][3];

    float v0 = fec + fe0, v1 = fec + fe1, v2 = fec + fe2;
    v0 = v0 > 0.f ? v0 : 0.2f * v0;
    v1 = v1 > 0.f ? v1 : 0.2f * v1;
    v2 = v2 > 0.f ? v2 : 0.2f * v2;
    float mx = fmaxf(v0, fmaxf(v1, v2));
    float x0 = expf(v0 - mx), x1 = expf(v1 - mx), x2 = expf(v2 - mx);
    float inv = 1.f / (x0 + x1 + x2);
    float a0 = x0 * inv, a1 = x1 * inv, a2 = x2 * inv;

    uint2* mp = (uint2*)(g_mixh + (size_t)n * FEAT);
    #pragma unroll
    for (int j = 0; j < 2; ++j) {
        int idx = half * 64 + lane + 32 * j;
        float4 m;
        m.x = s[j].x + a0*n0[j].x + a1*n1[j].x + a2*n2[j].x;
        m.y = s[j].y + a0*n0[j].y + a1*n1[j].y + a2*n2[j].y;
        m.z = s[j].z + a0*n0[j].z + a1*n1[j].z + a2*n2[j].z;
        m.w = s[j].w + a0*n0[j].w + a1*n1[j].w + a2*n2[j].w;
        __half2 h0 = __floats2half2_rn(m.x, m.y);
        __half2 h1 = __floats2half2_rn(m.z, m.w);
        uint2 p;
        p.x = *(unsigned*)&h0;  p.y = *(unsigned*)&h1;
        mp[idx] = p;
    }

    if (half == 0 && lane == 0) {
        atomicAdd(&bs[0], a0); atomicAdd(&bs[1], a1); atomicAdd(&bs[2], a2);
    }
    __syncthreads();
    if (tid < NREL) atomicAdd(&g_s[tid], (double)bs[tid]);
}

// ---- kernel 2: fp16 mma.sync GEMM with ldmatrix + 2-stage double buffer ----
// out[col][row] = relu( sum_k mix[row][k] * W[col][k] ); 8 warps 2m x 4n.
__global__ __launch_bounds__(256)
void gemm_kernel(float* __restrict__ out) {
    __shared__ __align__(16) char sm[40960];
    const int tid  = threadIdx.x;
    const int wid  = tid >> 5, lane = tid & 31;
    const int wm   = wid >> 2;   // 0..1
    const int wn   = wid & 3;    // 0..3
    const int g    = lane >> 2;
    const int tg   = lane & 3;

    const size_t rowBlk = (size_t)blockIdx.y * 128;   // nodes
    const int    colBlk = blockIdx.x * 128;           // embed
    const __half* Aptr = g_mixh + rowBlk * FEAT;
    const __half* Bp   = g_Wh + (size_t)colBlk * FEAT;

    const uint32_t base = smem_u32(sm);
    char* const pA[2] = { sm,          sm + 20480 };
    char* const pB[2] = { sm + 10240,  sm + 30720 };
    const uint32_t uA[2] = { base,          base + 20480 };
    const uint32_t uB[2] = { base + 10240,  base + 30720 };

    const int r0  = tid >> 2;          // 0..63
    const int kq8 = (tid & 3) * 8;     // half offset within chunk
    const uint32_t st0 = (uint32_t)(r0 * 40 + kq8) * 2;
    const uint32_t st1 = st0 + 64 * 40 * 2;

    const uint32_t laneA = (uint32_t)(((lane & 15) * 40 + (lane >> 4) * 8) * 2);
    const uint32_t laneB = (uint32_t)((((lane & 7) + ((lane >> 4) << 3)) * 40
                                       + (((lane >> 3) & 1) << 3)) * 2);

    {
        uint4 a0 = *(const uint4*)(Aptr + (size_t)r0 * FEAT + kq8);
        uint4 a1 = *(const uint4*)(Aptr + (size_t)(r0 + 64) * FEAT + kq8);
        uint4 b0 = *(const uint4*)(Bp   + (size_t)r0 * FEAT + kq8);
        uint4 b1 = *(const uint4*)(Bp   + (size_t)(r0 + 64) * FEAT + kq8);
        *(uint4*)(pA[0] + st0) = a0;  *(uint4*)(pA[0] + st1) = a1;
        *(uint4*)(pB[0] + st0) = b0;  *(uint4*)(pB[0] + st1) = b1;
    }
    __syncthreads();

    float acc[4][4][4];
    #pragma unroll
    for (int i = 0; i < 4; ++i)
        #pragma unroll
        for (int j = 0; j < 4; ++j)
            #pragma unroll
            for (int q = 0; q < 4; ++q) acc[i][j][q] = 0.f;

    #pragma unroll 1
    for (int t = 0; t < NCHUNK; ++t) {
        const int st = t & 1;
        uint4 na0, na1, nb0, nb1;
        if (t < NCHUNK - 1) {
            int k0 = (t + 1) * BK;
            na0 = *(const uint4*)(Aptr + (size_t)r0 * FEAT + k0 + kq8);
            na1 = *(const uint4*)(Aptr + (size_t)(r0 + 64) * FEAT + k0 + kq8);
            nb0 = *(const uint4*)(Bp   + (size_t)r0 * FEAT + k0 + kq8);
            nb1 = *(const uint4*)(Bp   + (size_t)(r0 + 64) * FEAT + k0 + kq8);
        }

        #pragma unroll
        for (int kk = 0; kk < 2; ++kk) {
            unsigned af[4][4], bf[4][2];
            #pragma unroll
            for (int mt = 0; mt < 4; ++mt) {
                uint32_t addr = uA[st] + laneA
                              + (uint32_t)((((wm * 64 + mt * 16) * 40) + kk * 16) * 2);
                ldsm4(af[mt], addr);
            }
            #pragma unroll
            for (int p = 0; p < 2; ++p) {
                unsigned r[4];
                uint32_t addr = uB[st] + laneB
                              + (uint32_t)((((wn * 32 + p * 16) * 40) + kk * 16) * 2);
                ldsm4(r, addr);
                bf[2*p  ][0] = r[0];  bf[2*p  ][1] = r[1];
                bf[2*p+1][0] = r[2];  bf[2*p+1][1] = r[3];
            }
            #pragma unroll
            for (int mt = 0; mt < 4; ++mt)
                #pragma unroll
                for (int nt = 0; nt < 4; ++nt)
                    mma_f16(acc[mt][nt], af[mt], bf[nt]);
        }

        if (t < NCHUNK - 1) {
            const int ns = st ^ 1;
            *(uint4*)(pA[ns] + st0) = na0;  *(uint4*)(pA[ns] + st1) = na1;
            *(uint4*)(pB[ns] + st0) = nb0;  *(uint4*)(pB[ns] + st1) = nb1;
            __syncthreads();
        }
    }

    // epilogue: relu + transpose -> out[e][n]; Ts aliases the smem buffers
    float* Ts = (float*)sm;   // 32 x 132
    #pragma unroll 1
    for (int c = 0; c < 4; ++c) {
        __syncthreads();
        if (wn == c) {
            #pragma unroll
            for (int mt = 0; mt < 4; ++mt) {
                #pragma unroll
                for (int nt = 0; nt < 4; ++nt) {
                    int colL = nt * 8 + 2 * tg;
                    int rowL = wm * 64 + mt * 16 + g;
                    float q0 = acc[mt][nt][0], q1 = acc[mt][nt][1];
                    float q2 = acc[mt][nt][2], q3 = acc[mt][nt][3];
                    Ts[(colL    ) * 132 + rowL    ] = q0 > 0.f ? q0 : 0.f;
                    Ts[(colL + 1) * 132 + rowL    ] = q1 > 0.f ? q1 : 0.f;
                    Ts[(colL    ) * 132 + rowL + 8] = q2 > 0.f ? q2 : 0.f;
                    Ts[(colL + 1) * 132 + rowL + 8] = q3 > 0.f ? q3 : 0.f;
                }
            }
        }
        __syncthreads();
        int el  = tid >> 3;
        int f4i = tid & 7;
        size_t obase = (size_t)(colBlk + c * 32 + el) * NNODES + rowBlk;
        #pragma unroll
        for (int j = 0; j < 4; ++j) {
            float4 v = *(const float4*)&Ts[el * 132 + j * 32 + f4i * 4];
            *(float4*)&out[obase + j * 32 + f4i * 4] = v;
        }
    }

    // fused tail: softmax over 3 relation sums
    if (blockIdx.x == 0 && blockIdx.y == 0 && tid == 0) {
        double s0 = g_s[0], s1 = g_s[1], s2 = g_s[2];
        double m = fmax(s0, fmax(s1, s2));
        double e0 = exp(s0 - m), e1 = exp(s1 - m), e2 = exp(s2 - m);
        double inv = 1.0 / (e0 + e1 + e2);
        size_t obase2 = (size_t)EMB * NNODES;
        out[obase2 + 0] = (float)(e0 * inv);
        out[obase2 + 1] = (float)(e1 * inv);
        out[obase2 + 2] = (float)(e2 * inv);
    }
}

extern "C" void kernel_launch(void* const* d_in, const int* in_sizes, int n_in,
                              void* d_out, int out_size) {
    const float* selfF  = (const float*)d_in[0];
    const float* neighF = (const float*)d_in[1];
    const float* W      = (const float*)d_in[2];
    const float* a      = (const float*)d_in[3];
    float* out = (float*)d_out;

    wprep_kernel<<<64, 512>>>(W, a);
    prep2_kernel<<<4, 256>>>();
    mix_kernel<<<NNODES / 4, 256>>>(selfF, neighF);

    dim3 ggrid(EMB / 128, NNODES / 128);    // (4, 512)
    gemm_kernel<<<ggrid, 256>>>(out);
}

// round 8
// speedup vs baseline: 5.7748x; 1.1833x over previous
#include <cuda_runtime.h>
#include <cuda_fp16.h>
#include <cstdint>
#include <math.h>

#define NREL   3
#define NNODES 65536
#define FEAT   512
#define EMB    512
#define BK     32            // k halves per chunk
#define NCHUNK (FEAT/BK)     // 16
#define STAGES 4
#define STAGE_BYTES 20480    // A(10240) + B(10240), stride-40-half rows
#define SM_TOTAL (STAGES * STAGE_BYTES)   // 81920

// ---- scratch (static device globals; no allocations allowed) ----
__device__ __half  g_mixh[(size_t)NNODES * FEAT];  // 67 MB fp16 mixed features
__device__ __half  g_Wh[(size_t)EMB * FEAT];       // fp16 weight copy
__device__ float   g_u[2*EMB];
__device__ float   g_up[64 * 1024];                // prep partials
__device__ double  g_s[NREL];

__device__ __forceinline__ uint32_t smem_u32(const void* p) {
    uint32_t a;
    asm("{ .reg .u64 t; cvta.to.shared.u64 t, %1; cvt.u32.u64 %0, t; }" : "=r"(a) : "l"(p));
    return a;
}

__device__ __forceinline__ void mma_f16(float c[4], const unsigned a[4], const unsigned b[2]) {
    asm volatile(
        "mma.sync.aligned.m16n8k16.row.col.f32.f16.f16.f32 "
        "{%0,%1,%2,%3}, {%4,%5,%6,%7}, {%8,%9}, {%0,%1,%2,%3};\n"
        : "+f"(c[0]), "+f"(c[1]), "+f"(c[2]), "+f"(c[3])
        : "r"(a[0]), "r"(a[1]), "r"(a[2]), "r"(a[3]), "r"(b[0]), "r"(b[1]));
}

__device__ __forceinline__ void ldsm4(unsigned r[4], uint32_t addr) {
    asm volatile("ldmatrix.sync.aligned.m8n8.x4.shared.b16 {%0,%1,%2,%3}, [%4];"
        : "=r"(r[0]), "=r"(r[1]), "=r"(r[2]), "=r"(r[3]) : "r"(addr));
}

__device__ __forceinline__ void cpasync16(uint32_t smem, const void* g) {
    asm volatile("cp.async.cg.shared.global [%0], [%1], 16;" :: "r"(smem), "l"(g));
}
#define CP_COMMIT() asm volatile("cp.async.commit_group;" ::: "memory")
#define CP_WAIT(n)  asm volatile("cp.async.wait_group %0;" :: "n"(n) : "memory")

// ---- kernel 0a: W -> fp16 + partial u sums (8 e-rows per block) ----
__global__ __launch_bounds__(512)
void wprep_kernel(const float* __restrict__ W, const float* __restrict__ a) {
    int f = threadIdx.x;          // 0..511
    int b = blockIdx.x;           // 0..63
    int e0 = b * 8;
    float sc = 0.f, sn = 0.f;
    #pragma unroll
    for (int j = 0; j < 8; ++j) {
        float w = W[(size_t)(e0 + j) * FEAT + f];
        g_Wh[(size_t)(e0 + j) * FEAT + f] = __float2half_rn(w);
        sc += w * a[e0 + j];
        sn += w * a[EMB + e0 + j];
    }
    g_up[b * 1024 + f]       = sc;
    g_up[b * 1024 + 512 + f] = sn;
}

__global__ void prep2_kernel() {
    int i = blockIdx.x * 256 + threadIdx.x;   // 0..1023
    float s = 0.f;
    #pragma unroll
    for (int b = 0; b < 64; ++b) s += g_up[b * 1024 + i];
    g_u[i] = s;
    if (i < NREL) g_s[i] = 0.0;
}

// ---- kernel 1: per-node attention + feature mix (2 warps per node) ----
__global__ __launch_bounds__(256, 5)
void mix_kernel(const float* __restrict__ selfF, const float* __restrict__ neighF) {
    __shared__ float us[2 * EMB];
    __shared__ float dots[4][2][4];
    __shared__ float bs[NREL];

    const int tid  = threadIdx.x;
    const int lane = tid & 31;
    const int wid  = tid >> 5;
    const int nl   = wid >> 1;
    const int half = wid & 1;
    const int n    = blockIdx.x * 4 + nl;

    ((float4*)us)[tid] = ((const float4*)g_u)[tid];
    if (tid < NREL) bs[tid] = 0.f;
    __syncthreads();

    const float4* sp  = (const float4*)(selfF + (size_t)n * FEAT);
    const float4* np0 = (const float4*)(neighF + ((size_t)0 * NNODES + n) * FEAT);
    const float4* np1 = (const float4*)(neighF + ((size_t)1 * NNODES + n) * FEAT);
    const float4* np2 = (const float4*)(neighF + ((size_t)2 * NNODES + n) * FEAT);

    float4 s[2], n0[2], n1[2], n2[2];
    #pragma unroll
    for (int j = 0; j < 2; ++j) {
        int idx = half * 64 + lane + 32 * j;
        s[j]  = sp[idx];
        n0[j] = np0[idx];
        n1[j] = np1[idx];
        n2[j] = np2[idx];
    }

    float ec = 0.f, e0 = 0.f, e1 = 0.f, e2 = 0.f;
    #pragma unroll
    for (int j = 0; j < 2; ++j) {
        int idx = half * 64 + lane + 32 * j;
        float4 uc = ((const float4*)us)[idx];
        float4 un = ((const float4*)us)[128 + idx];
        ec += s[j].x*uc.x + s[j].y*uc.y + s[j].z*uc.z + s[j].w*uc.w;
        e0 += n0[j].x*un.x + n0[j].y*un.y + n0[j].z*un.z + n0[j].w*un.w;
        e1 += n1[j].x*un.x + n1[j].y*un.y + n1[j].z*un.z + n1[j].w*un.w;
        e2 += n2[j].x*un.x + n2[j].y*un.y + n2[j].z*un.z + n2[j].w*un.w;
    }
    #pragma unroll
    for (int o = 16; o; o >>= 1) {
        ec += __shfl_xor_sync(0xffffffffu, ec, o);
        e0 += __shfl_xor_sync(0xffffffffu, e0, o);
        e1 += __shfl_xor_sync(0xffffffffu, e1, o);
        e2 += __shfl_xor_sync(0xffffffffu, e2, o);
    }
    if (lane == 0) {
        dots[nl][half][0] = ec;
        dots[nl][half][1] = e0;
        dots[nl][half][2] = e1;
        dots[nl][half][3] = e2;
    }
    __syncthreads();

    float fec = dots[nl][0][0] + dots[nl][1][0];
    float fe0 = dots[nl][0][1] + dots[nl][1][1];
    float fe1 = dots[nl][0][2] + dots[nl][1][2];
    float fe2 = dots[nl][0][3] + dots[nl][1][3];

    float v0 = fec + fe0, v1 = fec + fe1, v2 = fec + fe2;
    v0 = v0 > 0.f ? v0 : 0.2f * v0;
    v1 = v1 > 0.f ? v1 : 0.2f * v1;
    v2 = v2 > 0.f ? v2 : 0.2f * v2;
    float mx = fmaxf(v0, fmaxf(v1, v2));
    float x0 = expf(v0 - mx), x1 = expf(v1 - mx), x2 = expf(v2 - mx);
    float inv = 1.f / (x0 + x1 + x2);
    float a0 = x0 * inv, a1 = x1 * inv, a2 = x2 * inv;

    uint2* mp = (uint2*)(g_mixh + (size_t)n * FEAT);
    #pragma unroll
    for (int j = 0; j < 2; ++j) {
        int idx = half * 64 + lane + 32 * j;
        float4 m;
        m.x = s[j].x + a0*n0[j].x + a1*n1[j].x + a2*n2[j].x;
        m.y = s[j].y + a0*n0[j].y + a1*n1[j].y + a2*n2[j].y;
        m.z = s[j].z + a0*n0[j].z + a1*n1[j].z + a2*n2[j].z;
        m.w = s[j].w + a0*n0[j].w + a1*n1[j].w + a2*n2[j].w;
        __half2 h0 = __floats2half2_rn(m.x, m.y);
        __half2 h1 = __floats2half2_rn(m.z, m.w);
        uint2 p;
        p.x = *(unsigned*)&h0;  p.y = *(unsigned*)&h1;
        mp[idx] = p;
    }

    if (half == 0 && lane == 0) {
        atomicAdd(&bs[0], a0); atomicAdd(&bs[1], a1); atomicAdd(&bs[2], a2);
    }
    __syncthreads();
    if (tid < NREL) atomicAdd(&g_s[tid], (double)bs[tid]);
}

// ---- kernel 2: fp16 mma.sync GEMM; cp.async 4-stage ring + ldmatrix ----
// out[col][row] = relu( sum_k mix[row][k] * W[col][k] ); 8 warps 2m x 4n.
__global__ __launch_bounds__(256)
void gemm_kernel(float* __restrict__ out) {
    extern __shared__ __align__(16) char sm[];
    const int tid  = threadIdx.x;
    const int wid  = tid >> 5, lane = tid & 31;
    const int wm   = wid >> 2;   // 0..1
    const int wn   = wid & 3;    // 0..3
    const int g    = lane >> 2;
    const int tg   = lane & 3;

    const size_t rowBlk = (size_t)blockIdx.y * 128;   // nodes
    const int    colBlk = blockIdx.x * 128;           // embed
    const __half* Aptr = g_mixh + rowBlk * FEAT;
    const __half* Bp   = g_Wh + (size_t)colBlk * FEAT;

    const uint32_t base = smem_u32(sm);

    const int r0  = tid >> 2;          // 0..63
    const int kq8 = (tid & 3) * 8;     // half offset within chunk
    const uint32_t st0 = (uint32_t)(r0 * 40 + kq8) * 2;
    const uint32_t st1 = st0 + 64 * 40 * 2;

    const uint32_t laneA = (uint32_t)(((lane & 15) * 40 + (lane >> 4) * 8) * 2);
    const uint32_t laneB = (uint32_t)((((lane & 7) + ((lane >> 4) << 3)) * 40
                                       + (((lane >> 3) & 1) << 3)) * 2);

    const __half* gA0 = Aptr + (size_t)r0 * FEAT + kq8;
    const __half* gA1 = Aptr + (size_t)(r0 + 64) * FEAT + kq8;
    const __half* gB0 = Bp   + (size_t)r0 * FEAT + kq8;
    const __half* gB1 = Bp   + (size_t)(r0 + 64) * FEAT + kq8;

    // prologue: issue STAGES-1 chunks
    #pragma unroll
    for (int t = 0; t < STAGES - 1; ++t) {
        uint32_t sA = base + t * STAGE_BYTES;
        uint32_t sB = sA + 10240;
        int k0 = t * BK;
        cpasync16(sA + st0, gA0 + k0);
        cpasync16(sA + st1, gA1 + k0);
        cpasync16(sB + st0, gB0 + k0);
        cpasync16(sB + st1, gB1 + k0);
        CP_COMMIT();
    }

    float acc[4][4][4];
    #pragma unroll
    for (int i = 0; i < 4; ++i)
        #pragma unroll
        for (int j = 0; j < 4; ++j)
            #pragma unroll
            for (int q = 0; q < 4; ++q) acc[i][j][q] = 0.f;

    #pragma unroll 1
    for (int t = 0; t < NCHUNK; ++t) {
        CP_WAIT(STAGES - 2);
        __syncthreads();

        const int slot = t & (STAGES - 1);
        const uint32_t uA = base + slot * STAGE_BYTES;
        const uint32_t uB = uA + 10240;

        #pragma unroll
        for (int kk = 0; kk < 2; ++kk) {
            unsigned af[4][4], bf[4][2];
            #pragma unroll
            for (int mt = 0; mt < 4; ++mt) {
                uint32_t addr = uA + laneA
                              + (uint32_t)((((wm * 64 + mt * 16) * 40) + kk * 16) * 2);
                ldsm4(af[mt], addr);
            }
            #pragma unroll
            for (int p = 0; p < 2; ++p) {
                unsigned r[4];
                uint32_t addr = uB + laneB
                              + (uint32_t)((((wn * 32 + p * 16) * 40) + kk * 16) * 2);
                ldsm4(r, addr);
                bf[2*p  ][0] = r[0];  bf[2*p  ][1] = r[1];
                bf[2*p+1][0] = r[2];  bf[2*p+1][1] = r[3];
            }
            #pragma unroll
            for (int mt = 0; mt < 4; ++mt)
                #pragma unroll
                for (int nt = 0; nt < 4; ++nt)
                    mma_f16(acc[mt][nt], af[mt], bf[nt]);
        }

        // issue chunk t+STAGES-1 into the slot freed by chunk t-1
        const int tn = t + STAGES - 1;
        if (tn < NCHUNK) {
            const int ns = tn & (STAGES - 1);
            uint32_t sA = base + ns * STAGE_BYTES;
            uint32_t sB = sA + 10240;
            int k0 = tn * BK;
            cpasync16(sA + st0, gA0 + k0);
            cpasync16(sA + st1, gA1 + k0);
            cpasync16(sB + st0, gB0 + k0);
            cpasync16(sB + st1, gB1 + k0);
        }
        CP_COMMIT();
    }

    // epilogue: relu + transpose -> out[e][n]; Ts aliases the ring buffer
    float* Ts = (float*)sm;   // 32 x 132
    #pragma unroll 1
    for (int c = 0; c < 4; ++c) {
        __syncthreads();
        if (wn == c) {
            #pragma unroll
            for (int mt = 0; mt < 4; ++mt) {
                #pragma unroll
                for (int nt = 0; nt < 4; ++nt) {
                    int colL = nt * 8 + 2 * tg;
                    int rowL = wm * 64 + mt * 16 + g;
                    float q0 = acc[mt][nt][0], q1 = acc[mt][nt][1];
                    float q2 = acc[mt][nt][2], q3 = acc[mt][nt][3];
                    Ts[(colL    ) * 132 + rowL    ] = q0 > 0.f ? q0 : 0.f;
                    Ts[(colL + 1) * 132 + rowL    ] = q1 > 0.f ? q1 : 0.f;
                    Ts[(colL    ) * 132 + rowL + 8] = q2 > 0.f ? q2 : 0.f;
                    Ts[(colL + 1) * 132 + rowL + 8] = q3 > 0.f ? q3 : 0.f;
                }
            }
        }
        __syncthreads();
        int el  = tid >> 3;
        int f4i = tid & 7;
        size_t obase = (size_t)(colBlk + c * 32 + el) * NNODES + rowBlk;
        #pragma unroll
        for (int j = 0; j < 4; ++j) {
            float4 v = *(const float4*)&Ts[el * 132 + j * 32 + f4i * 4];
            *(float4*)&out[obase + j * 32 + f4i * 4] = v;
        }
    }

    // fused tail: softmax over 3 relation sums
    if (blockIdx.x == 0 && blockIdx.y == 0 && tid == 0) {
        double s0 = g_s[0], s1 = g_s[1], s2 = g_s[2];
        double m = fmax(s0, fmax(s1, s2));
        double e0 = exp(s0 - m), e1 = exp(s1 - m), e2 = exp(s2 - m);
        double inv = 1.0 / (e0 + e1 + e2);
        size_t obase2 = (size_t)EMB * NNODES;
        out[obase2 + 0] = (float)(e0 * inv);
        out[obase2 + 1] = (float)(e1 * inv);
        out[obase2 + 2] = (float)(e2 * inv);
    }
}

extern "C" void kernel_launch(void* const* d_in, const int* in_sizes, int n_in,
                              void* d_out, int out_size) {
    const float* selfF  = (const float*)d_in[0];
    const float* neighF = (const float*)d_in[1];
    const float* W      = (const float*)d_in[2];
    const float* a      = (const float*)d_in[3];
    float* out = (float*)d_out;

    cudaFuncSetAttribute(gemm_kernel, cudaFuncAttributeMaxDynamicSharedMemorySize, SM_TOTAL);

    wprep_kernel<<<64, 512>>>(W, a);
    prep2_kernel<<<4, 256>>>();
    mix_kernel<<<NNODES / 4, 256>>>(selfF, neighF);

    dim3 ggrid(EMB / 128, NNODES / 128);    // (4, 512)
    gemm_kernel<<<ggrid, 256, SM_TOTAL>>>(out);
}